// round 6
// baseline (speedup 1.0000x reference)
#include <cuda_runtime.h>
#include <math.h>
#include <stdint.h>

// Problem dims (fixed by the reference)
#define T_TOK 8192          // B*S tokens
#define D_DIM 2048
#define M_DIM 1024
#define E_NUM 8
#define TOPK  2
#define TK    (T_TOK * TOPK)

// ---------------- static device scratch (no allocs allowed) ----------------
__device__ int   g_counts[E_NUM];
__device__ int   g_cursor[E_NUM];
__device__ int   g_offsets[E_NUM + 1];
__device__ int   g_expert_tk[TK];   // (t*2+k) -> expert id
__device__ float g_weights[TK];     // (t*2+k) -> router weight
__device__ int   g_pos_tk[TK];      // (t*2+k) -> sorted row position
__device__ int   g_row_token[TK];   // sorted row -> source token
__device__ float g_H[(size_t)TK * M_DIM];          // 64 MB intermediate
__device__ float g_outsorted[(size_t)TK * D_DIM];  // 128 MB expert outputs

// ---------------- init ----------------
__global__ void init_kernel() {
    int i = threadIdx.x;
    if (i < E_NUM) { g_counts[i] = 0; g_cursor[i] = 0; }
}

// ---------------- routing: one warp per token ----------------
__global__ __launch_bounds__(256) void route_kernel(
    const float* __restrict__ x, const float* __restrict__ wg)
{
    int warp = (blockIdx.x * blockDim.x + threadIdx.x) >> 5;
    int lane = threadIdx.x & 31;
    if (warp >= T_TOK) return;
    const float* xr = x + (size_t)warp * D_DIM;

    float acc[E_NUM];
#pragma unroll
    for (int e = 0; e < E_NUM; e++) acc[e] = 0.f;

    for (int i = lane; i < D_DIM; i += 32) {
        float xv = xr[i];
        const float4* wrow = (const float4*)(wg + (size_t)i * E_NUM);
        float4 w0 = wrow[0], w1 = wrow[1];
        acc[0] += xv * w0.x; acc[1] += xv * w0.y;
        acc[2] += xv * w0.z; acc[3] += xv * w0.w;
        acc[4] += xv * w1.x; acc[5] += xv * w1.y;
        acc[6] += xv * w1.z; acc[7] += xv * w1.w;
    }
#pragma unroll
    for (int e = 0; e < E_NUM; e++) {
#pragma unroll
        for (int off = 16; off > 0; off >>= 1)
            acc[e] += __shfl_xor_sync(0xffffffffu, acc[e], off);
    }
    if (lane == 0) {
        int e0 = 0; float l0 = acc[0];
#pragma unroll
        for (int e = 1; e < E_NUM; e++) if (acc[e] > l0) { l0 = acc[e]; e0 = e; }
        int e1 = -1; float l1 = -INFINITY;
#pragma unroll
        for (int e = 0; e < E_NUM; e++)
            if (e != e0 && acc[e] > l1) { l1 = acc[e]; e1 = e; }
        // softmax over {l0, l1}, l0 >= l1
        float w0 = 1.f / (1.f + expf(l1 - l0));
        float w1 = 1.f - w0;
        g_expert_tk[warp * 2 + 0] = e0;
        g_expert_tk[warp * 2 + 1] = e1;
        g_weights[warp * 2 + 0] = w0;
        g_weights[warp * 2 + 1] = w1;
        atomicAdd(&g_counts[e0], 1);
        atomicAdd(&g_counts[e1], 1);
    }
}

// ---------------- exclusive prefix over E=8 ----------------
__global__ void prefix_kernel() {
    if (threadIdx.x == 0) {
        int s = 0;
        for (int e = 0; e < E_NUM; e++) { g_offsets[e] = s; s += g_counts[e]; }
        g_offsets[E_NUM] = s;
    }
}

// ---------------- scatter: assign sorted row slots ----------------
__global__ __launch_bounds__(256) void scatter_kernel() {
    int i = blockIdx.x * blockDim.x + threadIdx.x;
    if (i >= TK) return;
    int e = g_expert_tk[i];
    int pos = g_offsets[e] + atomicAdd(&g_cursor[e], 1);
    g_row_token[pos] = i >> 1;
    g_pos_tk[i] = pos;
}

// ---------------- GEMM1: H = silu(Xg @ wi0[e]) * (Xg @ wi1[e]) ----------------
// Tiles: BM=128 rows, BN=64 cols (per matrix), BK=16. 256 threads, 8x4(+8x4)/thread.
#define G1_BM 128
#define G1_BN 64
#define G1_BK 16

__global__ __launch_bounds__(256) void gemm1_kernel(
    const float* __restrict__ x,
    const float* __restrict__ wi0,
    const float* __restrict__ wi1)
{
    int e = blockIdx.z;
    int row_beg = g_offsets[e];
    int row_end = g_offsets[e + 1];
    int row0 = row_beg + blockIdx.y * G1_BM;
    if (row0 >= row_end) return;
    int n0 = blockIdx.x * G1_BN;

    __shared__ float As[G1_BK][G1_BM];
    __shared__ float Bs0[G1_BK][G1_BN];
    __shared__ float Bs1[G1_BK][G1_BN];
    __shared__ int   toks[G1_BM];

    int tid = threadIdx.x;
    for (int i = tid; i < G1_BM; i += 256) {
        int r = row0 + i;
        toks[i] = (r < row_end) ? g_row_token[r] : -1;
    }
    __syncthreads();

    const float* Bg0 = wi0 + (size_t)e * D_DIM * M_DIM;
    const float* Bg1 = wi1 + (size_t)e * D_DIM * M_DIM;

    float accG[8][4], accU[8][4];
#pragma unroll
    for (int j = 0; j < 8; j++)
#pragma unroll
        for (int i = 0; i < 4; i++) { accG[j][i] = 0.f; accU[j][i] = 0.f; }

    int tx = tid & 15;   // 16 threads across n
    int ty = tid >> 4;   // 16 threads across m

    for (int k0 = 0; k0 < D_DIM; k0 += G1_BK) {
        // load A tile (gathered rows), transposed to As[k][m]
#pragma unroll
        for (int it = 0; it < 2; it++) {
            int idx = tid + it * 256;        // 0..511
            int m = idx >> 2;
            int c4 = (idx & 3) * 4;
            int tok = toks[m];
            float4 v = make_float4(0.f, 0.f, 0.f, 0.f);
            if (tok >= 0)
                v = *(const float4*)(x + (size_t)tok * D_DIM + k0 + c4);
            As[c4 + 0][m] = v.x; As[c4 + 1][m] = v.y;
            As[c4 + 2][m] = v.z; As[c4 + 3][m] = v.w;
        }
        // load B tiles: 16 x 64 each, one float4 per thread per matrix
        {
            int kidx = tid >> 4;
            int n4 = (tid & 15) * 4;
            *(float4*)&Bs0[kidx][n4] =
                *(const float4*)(Bg0 + (size_t)(k0 + kidx) * M_DIM + n0 + n4);
            *(float4*)&Bs1[kidx][n4] =
                *(const float4*)(Bg1 + (size_t)(k0 + kidx) * M_DIM + n0 + n4);
        }
        __syncthreads();
#pragma unroll
        for (int kk = 0; kk < G1_BK; kk++) {
            float a[8], b0[4], b1[4];
#pragma unroll
            for (int j = 0; j < 8; j++) a[j] = As[kk][ty * 8 + j];
#pragma unroll
            for (int i = 0; i < 4; i++) {
                b0[i] = Bs0[kk][tx * 4 + i];
                b1[i] = Bs1[kk][tx * 4 + i];
            }
#pragma unroll
            for (int j = 0; j < 8; j++)
#pragma unroll
                for (int i = 0; i < 4; i++) {
                    accG[j][i] += a[j] * b0[i];
                    accU[j][i] += a[j] * b1[i];
                }
        }
        __syncthreads();
    }

    // epilogue: silu(g) * u
#pragma unroll
    for (int j = 0; j < 8; j++) {
        int r = row0 + ty * 8 + j;
        if (r < row_end) {
            float* Hrow = g_H + (size_t)r * M_DIM + n0 + tx * 4;
#pragma unroll
            for (int i = 0; i < 4; i++) {
                float g = accG[j][i];
                float h = g / (1.f + expf(-g)) * accU[j][i];
                Hrow[i] = h;
            }
        }
    }
}

// ---------------- GEMM2: out_sorted = H @ wo[e] ----------------
// BM=128, BN=128, BK=16, 256 threads, 8x8/thread
#define G2_BM 128
#define G2_BN 128
#define G2_BK 16

__global__ __launch_bounds__(256) void gemm2_kernel(
    const float* __restrict__ wo)
{
    int e = blockIdx.z;
    int row_beg = g_offsets[e];
    int row_end = g_offsets[e + 1];
    int row0 = row_beg + blockIdx.y * G2_BM;
    if (row0 >= row_end) return;
    int n0 = blockIdx.x * G2_BN;

    __shared__ float As[G2_BK][G2_BM];
    __shared__ float Bs[G2_BK][G2_BN];

    int tid = threadIdx.x;
    const float* Bg = wo + (size_t)e * M_DIM * D_DIM;

    float acc[8][8];
#pragma unroll
    for (int j = 0; j < 8; j++)
#pragma unroll
        for (int i = 0; i < 8; i++) acc[j][i] = 0.f;

    int tx = tid & 15;   // 16 across n (x8)
    int ty = tid >> 4;   // 16 across m (x8)

    for (int k0 = 0; k0 < M_DIM; k0 += G2_BK) {
        // A tile: rows contiguous in g_H
#pragma unroll
        for (int it = 0; it < 2; it++) {
            int idx = tid + it * 256;
            int m = idx >> 2;
            int c4 = (idx & 3) * 4;
            int r = row0 + m;
            float4 v = make_float4(0.f, 0.f, 0.f, 0.f);
            if (r < row_end)
                v = *(const float4*)(g_H + (size_t)r * M_DIM + k0 + c4);
            As[c4 + 0][m] = v.x; As[c4 + 1][m] = v.y;
            As[c4 + 2][m] = v.z; As[c4 + 3][m] = v.w;
        }
        // B tile: 16 x 128 = 512 float4 over 256 threads
#pragma unroll
        for (int it = 0; it < 2; it++) {
            int idx = tid + it * 256;
            int kidx = idx >> 5;
            int n4 = (idx & 31) * 4;
            *(float4*)&Bs[kidx][n4] =
                *(const float4*)(Bg + (size_t)(k0 + kidx) * D_DIM + n0 + n4);
        }
        __syncthreads();
#pragma unroll
        for (int kk = 0; kk < G2_BK; kk++) {
            float a[8], b[8];
#pragma unroll
            for (int j = 0; j < 8; j++) a[j] = As[kk][ty * 8 + j];
#pragma unroll
            for (int i = 0; i < 8; i++) b[i] = Bs[kk][tx * 8 + i];
#pragma unroll
            for (int j = 0; j < 8; j++)
#pragma unroll
                for (int i = 0; i < 8; i++) acc[j][i] += a[j] * b[i];
        }
        __syncthreads();
    }

#pragma unroll
    for (int j = 0; j < 8; j++) {
        int r = row0 + ty * 8 + j;
        if (r < row_end) {
            float* orow = g_outsorted + (size_t)r * D_DIM + n0 + tx * 8;
#pragma unroll
            for (int i = 0; i < 8; i += 4) {
                float4 v = make_float4(acc[j][i], acc[j][i + 1],
                                       acc[j][i + 2], acc[j][i + 3]);
                *(float4*)(orow + i) = v;
            }
        }
    }
}

// ---------------- combine: out[t] = w0*row(p0) + w1*row(p1) ----------------
__global__ __launch_bounds__(256) void combine_kernel(float* __restrict__ out) {
    int i = blockIdx.x * blockDim.x + threadIdx.x;     // over T*D/4
    if (i >= T_TOK * (D_DIM / 4)) return;
    int t  = i / (D_DIM / 4);
    int d4 = i % (D_DIM / 4);
    int   p0 = g_pos_tk[t * 2 + 0];
    int   p1 = g_pos_tk[t * 2 + 1];
    float w0 = g_weights[t * 2 + 0];
    float w1 = g_weights[t * 2 + 1];
    float4 a = *(const float4*)(g_outsorted + (size_t)p0 * D_DIM + d4 * 4);
    float4 b = *(const float4*)(g_outsorted + (size_t)p1 * D_DIM + d4 * 4);
    float4 o;
    o.x = w0 * a.x + w1 * b.x;
    o.y = w0 * a.y + w1 * b.y;
    o.z = w0 * a.z + w1 * b.z;
    o.w = w0 * a.w + w1 * b.w;
    *(float4*)(out + (size_t)t * D_DIM + d4 * 4) = o;
}

// ---------------- launch ----------------
extern "C" void kernel_launch(void* const* d_in, const int* in_sizes, int n_in,
                              void* d_out, int out_size)
{
    const float* x      = (const float*)d_in[0];   // [T, D]
    const float* w_gate = (const float*)d_in[1];   // [D, E]
    const float* wi_0   = (const float*)d_in[2];   // [E, D, M]
    const float* wi_1   = (const float*)d_in[3];   // [E, D, M]
    const float* wo     = (const float*)d_in[4];   // [E, M, D]
    float* out = (float*)d_out;

    init_kernel<<<1, 32>>>();
    route_kernel<<<(T_TOK * 32 + 255) / 256, 256>>>(x, w_gate);
    prefix_kernel<<<1, 32>>>();
    scatter_kernel<<<(TK + 255) / 256, 256>>>();

    // GEMM1: grid covers worst-case rows per expert; empty tiles early-exit
    dim3 g1(M_DIM / G1_BN, (TK + G1_BM - 1) / G1_BM, E_NUM);
    gemm1_kernel<<<g1, 256>>>(x, wi_0, wi_1);

    dim3 g2(D_DIM / G2_BN, (TK + G2_BM - 1) / G2_BM, E_NUM);
    gemm2_kernel<<<g2, 256>>>(wo);

    combine_kernel<<<(T_TOK * (D_DIM / 4) + 255) / 256, 256>>>(out);
}

// round 7
// speedup vs baseline: 1.0012x; 1.0012x over previous
#include <cuda_runtime.h>
#include <math.h>
#include <stdint.h>

// Problem dims (fixed by the reference)
#define T_TOK 8192          // B*S tokens
#define D_DIM 2048
#define M_DIM 1024
#define E_NUM 8
#define TOPK  2
#define TK    (T_TOK * TOPK)

// ---------------- static device scratch (no allocs allowed) ----------------
__device__ int   g_counts[E_NUM];
__device__ int   g_cursor[E_NUM];
__device__ int   g_offsets[E_NUM + 1];
__device__ int   g_expert_tk[TK];   // (t*2+k) -> expert id
__device__ float g_weights[TK];     // (t*2+k) -> router weight
__device__ int   g_pos_tk[TK];      // (t*2+k) -> sorted row position
__device__ int   g_row_token[TK];   // sorted row -> source token
__device__ float g_H[(size_t)TK * M_DIM];          // 64 MB intermediate
__device__ float g_outsorted[(size_t)TK * D_DIM];  // 128 MB expert outputs

// ---------------- init ----------------
__global__ void init_kernel() {
    int i = threadIdx.x;
    if (i < E_NUM) { g_counts[i] = 0; g_cursor[i] = 0; }
}

// ---------------- routing: one warp per token ----------------
__global__ __launch_bounds__(256) void route_kernel(
    const float* __restrict__ x, const float* __restrict__ wg)
{
    int warp = (blockIdx.x * blockDim.x + threadIdx.x) >> 5;
    int lane = threadIdx.x & 31;
    if (warp >= T_TOK) return;
    const float* xr = x + (size_t)warp * D_DIM;

    float acc[E_NUM];
#pragma unroll
    for (int e = 0; e < E_NUM; e++) acc[e] = 0.f;

    for (int i = lane; i < D_DIM; i += 32) {
        float xv = xr[i];
        const float4* wrow = (const float4*)(wg + (size_t)i * E_NUM);
        float4 w0 = wrow[0], w1 = wrow[1];
        acc[0] += xv * w0.x; acc[1] += xv * w0.y;
        acc[2] += xv * w0.z; acc[3] += xv * w0.w;
        acc[4] += xv * w1.x; acc[5] += xv * w1.y;
        acc[6] += xv * w1.z; acc[7] += xv * w1.w;
    }
#pragma unroll
    for (int e = 0; e < E_NUM; e++) {
#pragma unroll
        for (int off = 16; off > 0; off >>= 1)
            acc[e] += __shfl_xor_sync(0xffffffffu, acc[e], off);
    }
    if (lane == 0) {
        int e0 = 0; float l0 = acc[0];
#pragma unroll
        for (int e = 1; e < E_NUM; e++) if (acc[e] > l0) { l0 = acc[e]; e0 = e; }
        int e1 = -1; float l1 = -INFINITY;
#pragma unroll
        for (int e = 0; e < E_NUM; e++)
            if (e != e0 && acc[e] > l1) { l1 = acc[e]; e1 = e; }
        // softmax over {l0, l1}, l0 >= l1
        float w0 = 1.f / (1.f + expf(l1 - l0));
        float w1 = 1.f - w0;
        g_expert_tk[warp * 2 + 0] = e0;
        g_expert_tk[warp * 2 + 1] = e1;
        g_weights[warp * 2 + 0] = w0;
        g_weights[warp * 2 + 1] = w1;
        atomicAdd(&g_counts[e0], 1);
        atomicAdd(&g_counts[e1], 1);
    }
}

// ---------------- exclusive prefix over E=8 ----------------
__global__ void prefix_kernel() {
    if (threadIdx.x == 0) {
        int s = 0;
        for (int e = 0; e < E_NUM; e++) { g_offsets[e] = s; s += g_counts[e]; }
        g_offsets[E_NUM] = s;
    }
}

// ---------------- scatter: assign sorted row slots ----------------
__global__ __launch_bounds__(256) void scatter_kernel() {
    int i = blockIdx.x * blockDim.x + threadIdx.x;
    if (i >= TK) return;
    int e = g_expert_tk[i];
    int pos = g_offsets[e] + atomicAdd(&g_cursor[e], 1);
    g_row_token[pos] = i >> 1;
    g_pos_tk[i] = pos;
}

// ---------------- GEMM1: H = silu(Xg @ wi0[e]) * (Xg @ wi1[e]) ----------------
// Tiles: BM=128 rows, BN=64 cols (per matrix), BK=16. 256 threads, 8x4(+8x4)/thread.
#define G1_BM 128
#define G1_BN 64
#define G1_BK 16

__global__ __launch_bounds__(256) void gemm1_kernel(
    const float* __restrict__ x,
    const float* __restrict__ wi0,
    const float* __restrict__ wi1)
{
    int e = blockIdx.z;
    int row_beg = g_offsets[e];
    int row_end = g_offsets[e + 1];
    int row0 = row_beg + blockIdx.y * G1_BM;
    if (row0 >= row_end) return;
    int n0 = blockIdx.x * G1_BN;

    __shared__ float As[G1_BK][G1_BM];
    __shared__ float Bs0[G1_BK][G1_BN];
    __shared__ float Bs1[G1_BK][G1_BN];
    __shared__ int   toks[G1_BM];

    int tid = threadIdx.x;
    for (int i = tid; i < G1_BM; i += 256) {
        int r = row0 + i;
        toks[i] = (r < row_end) ? g_row_token[r] : -1;
    }
    __syncthreads();

    const float* Bg0 = wi0 + (size_t)e * D_DIM * M_DIM;
    const float* Bg1 = wi1 + (size_t)e * D_DIM * M_DIM;

    float accG[8][4], accU[8][4];
#pragma unroll
    for (int j = 0; j < 8; j++)
#pragma unroll
        for (int i = 0; i < 4; i++) { accG[j][i] = 0.f; accU[j][i] = 0.f; }

    int tx = tid & 15;   // 16 threads across n
    int ty = tid >> 4;   // 16 threads across m

    for (int k0 = 0; k0 < D_DIM; k0 += G1_BK) {
        // load A tile (gathered rows), transposed to As[k][m]
#pragma unroll
        for (int it = 0; it < 2; it++) {
            int idx = tid + it * 256;        // 0..511
            int m = idx >> 2;
            int c4 = (idx & 3) * 4;
            int tok = toks[m];
            float4 v = make_float4(0.f, 0.f, 0.f, 0.f);
            if (tok >= 0)
                v = *(const float4*)(x + (size_t)tok * D_DIM + k0 + c4);
            As[c4 + 0][m] = v.x; As[c4 + 1][m] = v.y;
            As[c4 + 2][m] = v.z; As[c4 + 3][m] = v.w;
        }
        // load B tiles: 16 x 64 each, one float4 per thread per matrix
        {
            int kidx = tid >> 4;
            int n4 = (tid & 15) * 4;
            *(float4*)&Bs0[kidx][n4] =
                *(const float4*)(Bg0 + (size_t)(k0 + kidx) * M_DIM + n0 + n4);
            *(float4*)&Bs1[kidx][n4] =
                *(const float4*)(Bg1 + (size_t)(k0 + kidx) * M_DIM + n0 + n4);
        }
        __syncthreads();
#pragma unroll
        for (int kk = 0; kk < G1_BK; kk++) {
            float a[8], b0[4], b1[4];
#pragma unroll
            for (int j = 0; j < 8; j++) a[j] = As[kk][ty * 8 + j];
#pragma unroll
            for (int i = 0; i < 4; i++) {
                b0[i] = Bs0[kk][tx * 4 + i];
                b1[i] = Bs1[kk][tx * 4 + i];
            }
#pragma unroll
            for (int j = 0; j < 8; j++)
#pragma unroll
                for (int i = 0; i < 4; i++) {
                    accG[j][i] += a[j] * b0[i];
                    accU[j][i] += a[j] * b1[i];
                }
        }
        __syncthreads();
    }

    // epilogue: silu(g) * u
#pragma unroll
    for (int j = 0; j < 8; j++) {
        int r = row0 + ty * 8 + j;
        if (r < row_end) {
            float* Hrow = g_H + (size_t)r * M_DIM + n0 + tx * 4;
#pragma unroll
            for (int i = 0; i < 4; i++) {
                float g = accG[j][i];
                float h = g / (1.f + expf(-g)) * accU[j][i];
                Hrow[i] = h;
            }
        }
    }
}

// ---------------- GEMM2: out_sorted = H @ wo[e] ----------------
// BM=128, BN=128, BK=16, 256 threads, 8x8/thread
#define G2_BM 128
#define G2_BN 128
#define G2_BK 16

__global__ __launch_bounds__(256) void gemm2_kernel(
    const float* __restrict__ wo)
{
    int e = blockIdx.z;
    int row_beg = g_offsets[e];
    int row_end = g_offsets[e + 1];
    int row0 = row_beg + blockIdx.y * G2_BM;
    if (row0 >= row_end) return;
    int n0 = blockIdx.x * G2_BN;

    __shared__ float As[G2_BK][G2_BM];
    __shared__ float Bs[G2_BK][G2_BN];

    int tid = threadIdx.x;
    const float* Bg = wo + (size_t)e * M_DIM * D_DIM;

    float acc[8][8];
#pragma unroll
    for (int j = 0; j < 8; j++)
#pragma unroll
        for (int i = 0; i < 8; i++) acc[j][i] = 0.f;

    int tx = tid & 15;   // 16 across n (x8)
    int ty = tid >> 4;   // 16 across m (x8)

    for (int k0 = 0; k0 < M_DIM; k0 += G2_BK) {
        // A tile: rows contiguous in g_H
#pragma unroll
        for (int it = 0; it < 2; it++) {
            int idx = tid + it * 256;
            int m = idx >> 2;
            int c4 = (idx & 3) * 4;
            int r = row0 + m;
            float4 v = make_float4(0.f, 0.f, 0.f, 0.f);
            if (r < row_end)
                v = *(const float4*)(g_H + (size_t)r * M_DIM + k0 + c4);
            As[c4 + 0][m] = v.x; As[c4 + 1][m] = v.y;
            As[c4 + 2][m] = v.z; As[c4 + 3][m] = v.w;
        }
        // B tile: 16 x 128 = 512 float4 over 256 threads
#pragma unroll
        for (int it = 0; it < 2; it++) {
            int idx = tid + it * 256;
            int kidx = idx >> 5;
            int n4 = (idx & 31) * 4;
            *(float4*)&Bs[kidx][n4] =
                *(const float4*)(Bg + (size_t)(k0 + kidx) * D_DIM + n0 + n4);
        }
        __syncthreads();
#pragma unroll
        for (int kk = 0; kk < G2_BK; kk++) {
            float a[8], b[8];
#pragma unroll
            for (int j = 0; j < 8; j++) a[j] = As[kk][ty * 8 + j];
#pragma unroll
            for (int i = 0; i < 8; i++) b[i] = Bs[kk][tx * 8 + i];
#pragma unroll
            for (int j = 0; j < 8; j++)
#pragma unroll
                for (int i = 0; i < 8; i++) acc[j][i] += a[j] * b[i];
        }
        __syncthreads();
    }

#pragma unroll
    for (int j = 0; j < 8; j++) {
        int r = row0 + ty * 8 + j;
        if (r < row_end) {
            float* orow = g_outsorted + (size_t)r * D_DIM + n0 + tx * 8;
#pragma unroll
            for (int i = 0; i < 8; i += 4) {
                float4 v = make_float4(acc[j][i], acc[j][i + 1],
                                       acc[j][i + 2], acc[j][i + 3]);
                *(float4*)(orow + i) = v;
            }
        }
    }
}

// ---------------- combine: out[t] = w0*row(p0) + w1*row(p1) ----------------
__global__ __launch_bounds__(256) void combine_kernel(float* __restrict__ out) {
    int i = blockIdx.x * blockDim.x + threadIdx.x;     // over T*D/4
    if (i >= T_TOK * (D_DIM / 4)) return;
    int t  = i / (D_DIM / 4);
    int d4 = i % (D_DIM / 4);
    int   p0 = g_pos_tk[t * 2 + 0];
    int   p1 = g_pos_tk[t * 2 + 1];
    float w0 = g_weights[t * 2 + 0];
    float w1 = g_weights[t * 2 + 1];
    float4 a = *(const float4*)(g_outsorted + (size_t)p0 * D_DIM + d4 * 4);
    float4 b = *(const float4*)(g_outsorted + (size_t)p1 * D_DIM + d4 * 4);
    float4 o;
    o.x = w0 * a.x + w1 * b.x;
    o.y = w0 * a.y + w1 * b.y;
    o.z = w0 * a.z + w1 * b.z;
    o.w = w0 * a.w + w1 * b.w;
    *(float4*)(out + (size_t)t * D_DIM + d4 * 4) = o;
}

// ---------------- launch ----------------
extern "C" void kernel_launch(void* const* d_in, const int* in_sizes, int n_in,
                              void* d_out, int out_size)
{
    const float* x      = (const float*)d_in[0];   // [T, D]
    const float* w_gate = (const float*)d_in[1];   // [D, E]
    const float* wi_0   = (const float*)d_in[2];   // [E, D, M]
    const float* wi_1   = (const float*)d_in[3];   // [E, D, M]
    const float* wo     = (const float*)d_in[4];   // [E, M, D]
    float* out = (float*)d_out;

    init_kernel<<<1, 32>>>();
    route_kernel<<<(T_TOK * 32 + 255) / 256, 256>>>(x, w_gate);
    prefix_kernel<<<1, 32>>>();
    scatter_kernel<<<(TK + 255) / 256, 256>>>();

    // GEMM1: grid covers worst-case rows per expert; empty tiles early-exit
    dim3 g1(M_DIM / G1_BN, (TK + G1_BM - 1) / G1_BM, E_NUM);
    gemm1_kernel<<<g1, 256>>>(x, wi_0, wi_1);

    dim3 g2(D_DIM / G2_BN, (TK + G2_BM - 1) / G2_BM, E_NUM);
    gemm2_kernel<<<g2, 256>>>(wo);

    combine_kernel<<<(T_TOK * (D_DIM / 4) + 255) / 256, 256>>>(out);
}